// round 6
// baseline (speedup 1.0000x reference)
#include <cuda_runtime.h>
#include <math.h>

#define Bn   2
#define Sn   2048
#define En   1024
#define Hn   16
#define Dn   64
#define NEXP 8
#define NTOK (Bn*Sn)          // 4096
#define BHn  (Bn*Hn)          // 32
#define ROTSTRIDE ((size_t)BHn*Sn*Dn)

// ---------------- scratch ----------------
__device__ float g_lin [(size_t)3*NTOK*En];
__device__ float g_rot [(size_t)3*BHn*Sn*Dn];
__device__ float g_vt  [(size_t)BHn*Dn*Sn];        // V transposed (bh, d, s)
__device__ float g_probs[(size_t)BHn*Sn*Sn];       // 512 MB
__device__ float g_attn[(size_t)NTOK*En];
__device__ float g_sel [(size_t)2*NTOK*En];
__device__ float g_moe [(size_t)NTOK*En];
__device__ float g_gateflat[2*NTOK];
__device__ int   g_list[NEXP*NTOK];
__device__ int   g_cnt [NEXP];

__global__ void zero_cnt_kernel() {
    if (threadIdx.x < NEXP) g_cnt[threadIdx.x] = 0;
}

// ---------------- tf32 helpers ----------------
__device__ __forceinline__ unsigned f2tf(float x) {
    unsigned r;
    asm("cvt.rna.tf32.f32 %0, %1;" : "=r"(r) : "f"(x));
    return r;
}
__device__ __forceinline__ void mma8(float* c, const unsigned* a, const unsigned* b) {
    asm volatile(
        "mma.sync.aligned.m16n8k8.row.col.f32.tf32.tf32.f32 "
        "{%0,%1,%2,%3}, {%4,%5,%6,%7}, {%8,%9}, {%0,%1,%2,%3};\n"
        : "+f"(c[0]), "+f"(c[1]), "+f"(c[2]), "+f"(c[3])
        : "r"(a[0]), "r"(a[1]), "r"(a[2]), "r"(a[3]), "r"(b[0]), "r"(b[1]));
}
template<int SPLIT>
__device__ __forceinline__ uint2 pack_tf(float v) {
    unsigned hi = f2tf(v);
    unsigned lo = 0u;
    if (SPLIT) lo = f2tf(v - __uint_as_float(hi));
    return make_uint2(hi, lo);
}

// ---------------- pipelined packed-tf32 GEMM ----------------
// C[z] = alpha * A[z][M][K] * B[z][N][K]^T (+bias) (+resid)
// MODE 0: plain   MODE 1: QKV (z picks B/bias, C plane)
// MODE 2: PV scatter into head layout   MODE 3: expert gather/scatter
template<int BN, int SPLIT, int MODE>
__global__ void __launch_bounds__(256)
gemm_pk(const float* __restrict__ A0,
        const float* __restrict__ B0, const float* __restrict__ B1,
        const float* __restrict__ B2,
        const float* __restrict__ bias0, const float* __restrict__ bias1,
        const float* __restrict__ bias2,
        const float* __restrict__ resid,
        float* __restrict__ Cg,
        int N, int K,
        long long sAz, long long sBz, long long sCz,
        float alpha)
{
    constexpr int WC   = (BN == 128) ? 4 : 2;
    constexpr int MT   = (BN == 128) ? 4 : 2;
    constexpr int ASTG = 128 * 32;
    constexpr int BSTG = BN * 32;
    constexpr int BL   = (BN * 32) / 1024;

    extern __shared__ uint2 sm[];
    uint2* Asm = sm;               // [2][ASTG]
    uint2* Bsm = sm + 2 * ASTG;    // [2][BSTG]

    __shared__ int   rowflat[128];
    __shared__ float rowgate[128];

    const int tid = threadIdx.x;
    const int z   = blockIdx.z;
    const int m0  = blockIdx.y * 128;
    const int n0  = blockIdx.x * BN;

    int cnt = 0;
    if (MODE == 3) {
        cnt = g_cnt[z];
        if (m0 >= cnt) return;
        if (tid < 128) {
            int m = m0 + tid;
            int fl = (m < cnt) ? g_list[z * NTOK + m] : 0;
            rowflat[tid] = fl;
            rowgate[tid] = (m < cnt) ? g_gateflat[fl] : 0.f;
        }
        __syncthreads();
    }

    const float* A = A0 + (size_t)z * sAz;
    const float* B;
    const float* bias;
    if (MODE == 1) {
        B    = (z == 0) ? B0 : ((z == 1) ? B1 : B2);
        bias = (z == 0) ? bias0 : ((z == 1) ? bias1 : bias2);
    } else if (MODE == 3) {
        B    = B0 + (size_t)z * sBz;
        bias = bias0 + (size_t)z * En;
    } else {
        B    = B0 + (size_t)z * sBz;
        bias = bias0;
    }

    // per-thread gmem pointers (fixed across k-tiles)
    const float* aP[4]; int aR[4], aC[4];
    #pragma unroll
    for (int l = 0; l < 4; l++) {
        int idx = l * 256 + tid;
        int r = idx >> 3, c4 = (idx & 7) << 2;
        aR[l] = r; aC[l] = c4;
        const float* base = (MODE == 3)
            ? (g_attn + (size_t)(rowflat[r] >> 1) * En)
            : (A + (size_t)(m0 + r) * K);
        aP[l] = base + c4;
    }
    const float* bP[BL]; int bR[BL], bC[BL];
    #pragma unroll
    for (int l = 0; l < BL; l++) {
        int idx = l * 256 + tid;
        int r = idx >> 3, c4 = (idx & 7) << 2;
        bR[l] = r; bC[l] = c4;
        bP[l] = B + (size_t)(n0 + r) * K + c4;
    }

    const int lane = tid & 31, warp = tid >> 5;
    const int grp  = lane >> 2, qd = lane & 3;
    const int m0w  = (warp / WC) * (16 * MT);
    const int n0w  = (warp % WC) * 32;
    const int sw   = grp << 2;

    float acc[MT][4][4];
    #pragma unroll
    for (int i = 0; i < MT; i++)
        #pragma unroll
        for (int j = 0; j < 4; j++)
            #pragma unroll
            for (int c = 0; c < 4; c++) acc[i][j][c] = 0.f;

    float4 ra[4], rb[BL];

    auto stash = [&](int stg) {
        #pragma unroll
        for (int l = 0; l < 4; l++) {
            uint2* d = Asm + stg * ASTG + aR[l] * 32;
            int s = (aR[l] & 7) << 2;
            d[(aC[l] + 0) ^ s] = pack_tf<SPLIT>(ra[l].x);
            d[(aC[l] + 1) ^ s] = pack_tf<SPLIT>(ra[l].y);
            d[(aC[l] + 2) ^ s] = pack_tf<SPLIT>(ra[l].z);
            d[(aC[l] + 3) ^ s] = pack_tf<SPLIT>(ra[l].w);
        }
        #pragma unroll
        for (int l = 0; l < BL; l++) {
            uint2* d = Bsm + stg * BSTG + bR[l] * 32;
            int s = (bR[l] & 7) << 2;
            d[(bC[l] + 0) ^ s] = pack_tf<SPLIT>(rb[l].x);
            d[(bC[l] + 1) ^ s] = pack_tf<SPLIT>(rb[l].y);
            d[(bC[l] + 2) ^ s] = pack_tf<SPLIT>(rb[l].z);
            d[(bC[l] + 3) ^ s] = pack_tf<SPLIT>(rb[l].w);
        }
    };

    // prologue
    #pragma unroll
    for (int l = 0; l < 4;  l++) ra[l] = *(const float4*)(aP[l]);
    #pragma unroll
    for (int l = 0; l < BL; l++) rb[l] = *(const float4*)(bP[l]);
    stash(0);
    __syncthreads();

    const int NTILE = K >> 5;
    for (int t = 0; t < NTILE; t++) {
        if (t + 1 < NTILE) {
            int off = (t + 1) << 5;
            #pragma unroll
            for (int l = 0; l < 4;  l++) ra[l] = *(const float4*)(aP[l] + off);
            #pragma unroll
            for (int l = 0; l < BL; l++) rb[l] = *(const float4*)(bP[l] + off);
        }
        const uint2* Ab = Asm + (t & 1) * ASTG + (m0w + grp) * 32;
        const uint2* Bb = Bsm + (t & 1) * BSTG + (n0w + grp) * 32;
        #pragma unroll
        for (int kk = 0; kk < 32; kk += 8) {
            int c0 = (kk + qd)     ^ sw;
            int c1 = (kk + qd + 4) ^ sw;
            uint2 bf[4][2];
            #pragma unroll
            for (int nt = 0; nt < 4; nt++) {
                bf[nt][0] = Bb[nt * 256 + c0];
                bf[nt][1] = Bb[nt * 256 + c1];
            }
            #pragma unroll
            for (int mt = 0; mt < MT; mt++) {
                const uint2* Ar = Ab + mt * 512;
                uint2 a0 = Ar[c0], a1 = Ar[256 + c0];
                uint2 a2 = Ar[c1], a3 = Ar[256 + c1];
                unsigned ah[4] = { a0.x, a1.x, a2.x, a3.x };
                #pragma unroll
                for (int nt = 0; nt < 4; nt++) {
                    unsigned bh2[2] = { bf[nt][0].x, bf[nt][1].x };
                    mma8(acc[mt][nt], ah, bh2);
                    if (SPLIT) {
                        unsigned al[4]  = { a0.y, a1.y, a2.y, a3.y };
                        unsigned bl2[2] = { bf[nt][0].y, bf[nt][1].y };
                        mma8(acc[mt][nt], al, bh2);
                        mma8(acc[mt][nt], ah, bl2);
                    }
                }
            }
        }
        if (t + 1 < NTILE) {
            stash((t + 1) & 1);
            __syncthreads();
        }
    }

    // epilogue
    #pragma unroll
    for (int mt = 0; mt < MT; mt++) {
        #pragma unroll
        for (int h = 0; h < 2; h++) {
            int mloc = m0w + mt * 16 + grp + h * 8;
            int r = m0 + mloc;
            if (MODE == 3 && r >= cnt) continue;
            #pragma unroll
            for (int nt = 0; nt < 4; nt++) {
                int col = n0w + nt * 8 + 2 * qd;
                int gc  = n0 + col;
                float v0 = acc[mt][nt][2 * h + 0] * alpha;
                float v1 = acc[mt][nt][2 * h + 1] * alpha;
                if (MODE == 3) {
                    float gtv = rowgate[mloc];
                    v0 = gtv * (v0 + bias[gc]);
                    v1 = gtv * (v1 + bias[gc + 1]);
                    *(float2*)(g_sel + (size_t)rowflat[mloc] * En + gc) =
                        make_float2(v0, v1);
                } else if (MODE == 2) {
                    int bb = z >> 4, hh = z & 15;
                    *(float2*)(Cg + ((size_t)(bb * Sn + r)) * En + hh * 64 + gc) =
                        make_float2(v0, v1);
                } else {
                    if (bias)  { v0 += bias[gc]; v1 += bias[gc + 1]; }
                    if (resid) {
                        const float* rr = resid + (size_t)r * N + gc;
                        v0 += rr[0]; v1 += rr[1];
                    }
                    float* dst = (MODE == 1)
                        ? (Cg + (size_t)z * ((size_t)NTOK * En) + (size_t)r * N + gc)
                        : (Cg + (size_t)z * sCz + (size_t)r * N + gc);
                    *(float2*)dst = make_float2(v0, v1);
                }
            }
        }
    }
}

// ---------------- RoPE + transpose ----------------
__global__ void rope_transpose_kernel()
{
    int idx = blockIdx.x * blockDim.x + threadIdx.x;
    int i = idx & 31;
    int h = (idx >> 5) & 15;
    int s = (idx >> 9) & (Sn - 1);
    int b = idx >> 20;

    float inv = powf(10000.0f, -(float)(2 * i) / 64.0f);
    float sn, cs;
    sincosf((float)s * inv, &sn, &cs);

    size_t in_base  = ((size_t)(b * Sn + s)) * En + h * 64;
    size_t out_base = ((size_t)((b * Hn + h) * Sn + s)) * 64;
    const size_t lin_stride = (size_t)NTOK * En;

    {
        const float* src = g_lin + in_base;
        float x1 = src[i], x2 = src[i + 32];
        g_rot[out_base + i]      = x1 * cs - x2 * sn;
        g_rot[out_base + i + 32] = x2 * cs + x1 * sn;
    }
    {
        const float* src = g_lin + lin_stride + in_base;
        float x1 = src[i], x2 = src[i + 32];
        g_rot[ROTSTRIDE + out_base + i]      = x1 * cs - x2 * sn;
        g_rot[ROTSTRIDE + out_base + i + 32] = x2 * cs + x1 * sn;
    }
    {
        const float* src = g_lin + 2 * lin_stride + in_base;
        g_rot[2 * ROTSTRIDE + out_base + i]      = src[i];
        g_rot[2 * ROTSTRIDE + out_base + i + 32] = src[i + 32];
    }
}

// ---------------- V transpose: (bh, s, d) -> (bh, d, s) ----------------
__global__ void __launch_bounds__(256)
vtrans_kernel()
{
    __shared__ float t[32][33];
    const int bh = blockIdx.z;
    const int s0 = blockIdx.x * 32;
    const int d0 = blockIdx.y * 32;
    const float* src = g_rot + 2 * ROTSTRIDE + (size_t)bh * Sn * Dn;
    float* dst = g_vt + (size_t)bh * Dn * Sn;
    const int tx = threadIdx.x & 31, ty = threadIdx.x >> 5;
    #pragma unroll
    for (int i = ty; i < 32; i += 8)
        t[i][tx] = src[(size_t)(s0 + i) * Dn + d0 + tx];
    __syncthreads();
    #pragma unroll
    for (int i = ty; i < 32; i += 8)
        dst[(size_t)(d0 + i) * Sn + s0 + tx] = t[tx][i];
}

// ---------------- row softmax (in place) ----------------
__global__ void __launch_bounds__(256)
softmax_kernel(float* __restrict__ probs)
{
    __shared__ float redm[8], reds[8];
    float4* p4 = (float4*)(probs + (size_t)blockIdx.x * Sn);
    const int tid = threadIdx.x;
    const int lane = tid & 31, warp = tid >> 5;

    float4 a = p4[tid], b = p4[tid + 256];
    float m = fmaxf(fmaxf(fmaxf(a.x, a.y), fmaxf(a.z, a.w)),
                    fmaxf(fmaxf(b.x, b.y), fmaxf(b.z, b.w)));
    #pragma unroll
    for (int o = 16; o; o >>= 1) m = fmaxf(m, __shfl_xor_sync(0xffffffffu, m, o));
    if (lane == 0) redm[warp] = m;
    __syncthreads();
    float mm = redm[0];
    #pragma unroll
    for (int w = 1; w < 8; w++) mm = fmaxf(mm, redm[w]);

    a.x = __expf(a.x - mm); a.y = __expf(a.y - mm);
    a.z = __expf(a.z - mm); a.w = __expf(a.w - mm);
    b.x = __expf(b.x - mm); b.y = __expf(b.y - mm);
    b.z = __expf(b.z - mm); b.w = __expf(b.w - mm);
    float s = (a.x + a.y + a.z + a.w) + (b.x + b.y + b.z + b.w);
    #pragma unroll
    for (int o = 16; o; o >>= 1) s += __shfl_xor_sync(0xffffffffu, s, o);
    if (lane == 0) reds[warp] = s;
    __syncthreads();
    float ss = 0.f;
    #pragma unroll
    for (int w = 0; w < 8; w++) ss += reds[w];
    float invs = 1.f / ss;

    a.x *= invs; a.y *= invs; a.z *= invs; a.w *= invs;
    b.x *= invs; b.y *= invs; b.z *= invs; b.w *= invs;
    p4[tid] = a; p4[tid + 256] = b;
}

// ---------------- gate + top-2 + dispatch ----------------
__global__ void __launch_bounds__(128)
gate_topk_kernel(const float* __restrict__ gw, const float* __restrict__ gb)
{
    const int warp = threadIdx.x >> 5;
    const int lane = threadIdx.x & 31;
    const int t = blockIdx.x * 4 + warp;

    float acc[NEXP];
    #pragma unroll
    for (int e = 0; e < NEXP; e++) acc[e] = 0.f;
    const float* xr = g_attn + (size_t)t * En;
    for (int i = lane; i < En; i += 32) {
        float xv = xr[i];
        #pragma unroll
        for (int e = 0; e < NEXP; e++) acc[e] += xv * gw[e * En + i];
    }
    #pragma unroll
    for (int e = 0; e < NEXP; e++) {
        #pragma unroll
        for (int off = 16; off; off >>= 1)
            acc[e] += __shfl_xor_sync(0xffffffffu, acc[e], off);
    }
    if (lane == 0) {
        float lg[NEXP];
        float m = -1e30f;
        #pragma unroll
        for (int e = 0; e < NEXP; e++) { lg[e] = acc[e] + gb[e]; m = fmaxf(m, lg[e]); }
        float sum = 0.f;
        #pragma unroll
        for (int e = 0; e < NEXP; e++) { lg[e] = __expf(lg[e] - m); sum += lg[e]; }
        float invs = 1.f / sum;
        int i0 = 0;
        #pragma unroll
        for (int e = 1; e < NEXP; e++) if (lg[e] > lg[i0]) i0 = e;
        int i1 = (i0 == 0) ? 1 : 0;
        #pragma unroll
        for (int e = 0; e < NEXP; e++) if (e != i0 && lg[e] > lg[i1]) i1 = e;

        int p0 = atomicAdd(&g_cnt[i0], 1);
        g_list[i0 * NTOK + p0] = t * 2;
        g_gateflat[t * 2] = lg[i0] * invs;
        int p1 = atomicAdd(&g_cnt[i1], 1);
        g_list[i1 * NTOK + p1] = t * 2 + 1;
        g_gateflat[t * 2 + 1] = lg[i1] * invs;
    }
}

// ---------------- combine expert slots ----------------
__global__ void combine_kernel()
{
    size_t i = (size_t)blockIdx.x * blockDim.x + threadIdx.x;
    size_t row = i >> 8;
    size_t col = i & 255;
    const float4* s4 = (const float4*)g_sel;
    float4 a = s4[(2 * row) * 256 + col];
    float4 b = s4[(2 * row + 1) * 256 + col];
    ((float4*)g_moe)[i] = make_float4(a.x + b.x, a.y + b.y, a.z + b.z, a.w + b.w);
}

// ---------------- launch ----------------
extern "C" void kernel_launch(void* const* d_in, const int* in_sizes, int n_in,
                              void* d_out, int out_size)
{
    const float* x     = (const float*)d_in[0];
    const float* q_w   = (const float*)d_in[1];
    const float* q_b   = (const float*)d_in[2];
    const float* k_w   = (const float*)d_in[3];
    const float* k_b   = (const float*)d_in[4];
    const float* v_w   = (const float*)d_in[5];
    const float* v_b   = (const float*)d_in[6];
    const float* gatew = (const float*)d_in[7];
    const float* gateb = (const float*)d_in[8];
    const float* ew    = (const float*)d_in[9];
    const float* eb    = (const float*)d_in[10];
    const float* ffn_w = (const float*)d_in[11];
    const float* ffn_b = (const float*)d_in[12];
    float* out = (float*)d_out;

    float *lin, *rot, *vt, *probs, *attn, *moe;
    cudaGetSymbolAddress((void**)&lin,   g_lin);
    cudaGetSymbolAddress((void**)&rot,   g_rot);
    cudaGetSymbolAddress((void**)&vt,    g_vt);
    cudaGetSymbolAddress((void**)&probs, g_probs);
    cudaGetSymbolAddress((void**)&attn,  g_attn);
    cudaGetSymbolAddress((void**)&moe,   g_moe);

    const int SM128 = 2 * (128 * 32 + 128 * 32) * 8;   // 131072
    const int SM64  = 2 * (128 * 32 +  64 * 32) * 8;   //  98304
    cudaFuncSetAttribute(gemm_pk<128,1,1>, cudaFuncAttributeMaxDynamicSharedMemorySize, SM128);
    cudaFuncSetAttribute(gemm_pk<128,1,0>, cudaFuncAttributeMaxDynamicSharedMemorySize, SM128);
    cudaFuncSetAttribute(gemm_pk< 64,1,2>, cudaFuncAttributeMaxDynamicSharedMemorySize, SM64);
    cudaFuncSetAttribute(gemm_pk<128,0,3>, cudaFuncAttributeMaxDynamicSharedMemorySize, SM128);
    cudaFuncSetAttribute(gemm_pk<128,0,0>, cudaFuncAttributeMaxDynamicSharedMemorySize, SM128);

    zero_cnt_kernel<<<1, 32>>>();

    // fused QKV projections (3xTF32): grid.z picks q/k/v
    gemm_pk<128,1,1><<<dim3(En/128, NTOK/128, 3), 256, SM128>>>(
        x, q_w, k_w, v_w, q_b, k_b, v_b, nullptr, lin,
        En, En, 0, 0, 0, 1.f);

    rope_transpose_kernel<<<(Bn * Sn * Hn * 32) / 256, 256>>>();
    vtrans_kernel<<<dim3(Sn/32, Dn/32, BHn), 256>>>();

    // scores = Q K^T / 8 (3xTF32)
    gemm_pk<128,1,0><<<dim3(Sn/128, Sn/128, BHn), 256, SM128>>>(
        rot, rot + ROTSTRIDE, nullptr, nullptr, nullptr, nullptr, nullptr, nullptr,
        probs, Sn, Dn,
        (long long)Sn * Dn, (long long)Sn * Dn, (long long)Sn * Sn, 0.125f);

    softmax_kernel<<<BHn * Sn, 256>>>(probs);

    // attn_out = P V (3xTF32), B = V^T, scatter into head layout
    gemm_pk<64,1,2><<<dim3(1, Sn/128, BHn), 256, SM64>>>(
        probs, vt, nullptr, nullptr, nullptr, nullptr, nullptr, nullptr,
        attn, Dn, Sn,
        (long long)Sn * Sn, (long long)Dn * Sn, 0, 1.f);

    gate_topk_kernel<<<NTOK / 4, 128>>>(gatew, gateb);

    // expert GEMM (plain tf32, gathered)
    gemm_pk<128,0,3><<<dim3(En/128, NTOK/128, NEXP), 256, SM128>>>(
        attn, ew, nullptr, nullptr, eb, nullptr, nullptr, nullptr,
        nullptr, En, En,
        0, (long long)En * En, 0, 1.f);

    combine_kernel<<<(NTOK * (En / 4)) / 256, 256>>>();

    // final FFN + bias + residual (plain tf32)
    gemm_pk<128,0,0><<<dim3(En/128, NTOK/128, 1), 256, SM128>>>(
        moe, ffn_w, nullptr, nullptr, ffn_b, nullptr, nullptr, x,
        out, En, En, 0, 0, 0, 1.f);
}